// round 15
// baseline (speedup 1.0000x reference)
#include <cuda_runtime.h>

#define P_BOX 512
#define N_PTS 50000
#define KMAX 64
#define HID 256
#define C_IMG 96
#define HF 160
#define WF 512
#define NPIX (HF*WF)
#define CAND_MAX 2048
#define FM_PIX 32
#define FM_GRID 304

typedef unsigned long long ull;

// ---------------- device scratch (no allocations allowed) ----------------
__device__ float g_fm[NPIX * HID];          // (H*W, 256) pixel-major
__device__ float g_tok[P_BOX * KMAX * 8];   // tokens
__device__ float g_refs[P_BOX * KMAX * 2];  // rx, ry
__device__ float g_vm[P_BOX * KMAX];        // projection-valid mask (0/1)
__device__ int   g_m[P_BOX];                // min(counts, 64)
__device__ float2 g_xy[N_PTS];              // SoA xy
__device__ float  g_z[N_PTS];               // SoA z
__device__ int   g_ctr;                     // persistent work counter
// packed weights, channel-pair layout:
//   g_pw[seg + j2*128 + c2] = (W[2j2][2c2], W[2j2+1][2c2], W[2j2][2c2+1], W[2j2+1][2c2+1])
// ulonglong2 view: .x = packed (row-pair) for channel 2c2, .y = for channel 2c2+1
__device__ float4 g_pw[81920];
#define PW_PE2 0
#define PW_QW  16384
#define PW_OW1 32768
#define PW_OW2 65536

// ---------------- f32x2 packed helpers ----------------
__device__ __forceinline__ ull ffma2(ull a, ull b, ull c) {
    ull d; asm("fma.rn.f32x2 %0, %1, %2, %3;" : "=l"(d) : "l"(a), "l"(b), "l"(c)); return d;
}
__device__ __forceinline__ ull pack2f(float x, float y) {
    ull d; asm("mov.b64 %0, {%1, %2};" : "=l"(d) : "f"(x), "f"(y)); return d;
}
__device__ __forceinline__ ull packdup(float x) {
    ull d; asm("mov.b64 %0, {%1, %1};" : "=l"(d) : "f"(x)); return d;
}
__device__ __forceinline__ float2 unpack2(ull v) {
    float2 r; asm("mov.b64 {%0, %1}, %2;" : "=f"(r.x), "=f"(r.y) : "l"(v)); return r;
}

// ---------------- kernel 0: AoS -> SoA prep + counter reset ----------------
__global__ void __launch_bounds__(256) k_prep(const float* __restrict__ pts) {
    int i = blockIdx.x * 256 + threadIdx.x;
    if (i == 0) g_ctr = 0;
    if (i < N_PTS) {
        g_xy[i] = make_float2(pts[i * 7], pts[i * 7 + 1]);
        g_z[i] = pts[i * 7 + 2];
    }
}

// ---------------- kernel 0b: all weight packing in ONE launch ----------------
__global__ void __launch_bounds__(128) k_wpack_all(const float* __restrict__ pe_w2,
                                                   const float* __restrict__ q_w,
                                                   const float* __restrict__ o_w1,
                                                   const float* __restrict__ o_w2) {
    int b = blockIdx.x, c2 = threadIdx.x;
    const float* W; int off, j2;
    if (b < 128)      { W = pe_w2; off = PW_PE2; j2 = b; }
    else if (b < 256) { W = q_w;   off = PW_QW;  j2 = b - 128; }
    else if (b < 512) { W = o_w1;  off = PW_OW1; j2 = b - 256; }
    else              { W = o_w2;  off = PW_OW2; j2 = b - 512; }
    const float* r0 = W + (2 * j2) * HID + 2 * c2;
    const float* r1 = W + (2 * j2 + 1) * HID + 2 * c2;
    g_pw[off + j2 * 128 + c2] = make_float4(r0[0], r1[0], r0[1], r1[1]);
}

// ---------------- kernel 1: fm = img^T @ f_w + f_b (persistent, f32x2) ----------------
__global__ void __launch_bounds__(256, 2) k_fm(const float* __restrict__ img,
                                               const float* __restrict__ fw,
                                               const float* __restrict__ fb) {
    extern __shared__ float smf[];
    float* w_s = smf;                 // 96*256, loaded once
    float* a_s = smf + C_IMG * HID;   // 96*FM_PIX, layout [c][pi], reloaded per tile
    int tid = threadIdx.x;
    for (int i = tid; i < C_IMG * HID; i += 256) w_s[i] = fw[i];
    float b = fb[tid];
    ull bb = pack2f(b, b);

    for (int t = blockIdx.x; t < NPIX / FM_PIX; t += FM_GRID) {
        int p0 = t * FM_PIX;
        __syncthreads();   // previous tile's a_s readers done (also covers w_s load on iter 0)
        for (int i = tid; i < C_IMG * FM_PIX; i += 256) {
            int c = i / FM_PIX, pi = i - c * FM_PIX;
            a_s[c * FM_PIX + pi] = img[c * NPIX + p0 + pi];
        }
        __syncthreads();
        ull acc[FM_PIX / 2];   // pixel pairs
#pragma unroll
        for (int i = 0; i < FM_PIX / 2; i++) acc[i] = bb;
#pragma unroll 4
        for (int c = 0; c < C_IMG; c++) {
            ull wd = packdup(w_s[c * HID + tid]);
            const ulonglong2* ap = (const ulonglong2*)&a_s[c * FM_PIX];
#pragma unroll
            for (int q = 0; q < FM_PIX / 4; q++) {
                ulonglong2 av = ap[q];
                acc[2 * q + 0] = ffma2(av.x, wd, acc[2 * q + 0]);
                acc[2 * q + 1] = ffma2(av.y, wd, acc[2 * q + 1]);
            }
        }
#pragma unroll
        for (int i = 0; i < FM_PIX / 2; i++) {
            float2 r = unpack2(acc[i]);
            g_fm[(p0 + 2 * i + 0) * HID + tid] = r.x;
            g_fm[(p0 + 2 * i + 1) * HID + tid] = r.y;
        }
    }
}

// ---------------- kernel 2: per-box selection + knn/density + projection ----------------
__global__ void __launch_bounds__(256) k_sel(const float* __restrict__ pts,
                                             const float* __restrict__ boxes,
                                             const float* __restrict__ proj,
                                             float* __restrict__ out_counts) {
    __shared__ unsigned long long keys[CAND_MAX];
    __shared__ int cnt_s;
    __shared__ int selidx[KMAX];
    __shared__ float nl_s[KMAX * 3];
    __shared__ float dmat[KMAX * KMAX];

    int p = blockIdx.x, tid = threadIdx.x;
    if (tid == 0) cnt_s = 0;
    __syncthreads();

    float cx = boxes[p * 7 + 0], cy = boxes[p * 7 + 1], cz = boxes[p * 7 + 2];
    float dx = boxes[p * 7 + 3], dy = boxes[p * 7 + 4], dz = boxes[p * 7 + 5];
    float yaw = boxes[p * 7 + 6];
    float cth = cosf(yaw), sth = sinf(yaw);
    float hx = dx * 0.5f, hy = dy * 0.5f, hz = dz * 0.5f;
    float ddx = fmaxf(dx, 0.001f), ddy = fmaxf(dy, 0.001f), ddz = fmaxf(dz, 0.001f);

    for (int i = tid; i < N_PTS; i += 256) {
        float2 xy = g_xy[i];
        float rx = xy.x - cx, ry = xy.y - cy;
        // explicit non-fused mul/add to track the reference's boundary decisions
        float lx = __fadd_rn(__fmul_rn(rx, cth), __fmul_rn(ry, sth));
        float ly = __fsub_rn(__fmul_rn(ry, cth), __fmul_rn(rx, sth));
        if (fabsf(lx) <= hx && fabsf(ly) <= hy) {
            float rz = g_z[i] - cz;
            if (fabsf(rz) <= hz) {
                float nx = lx / ddx, ny = ly / ddy;
                float planar = sqrtf(nx * nx + ny * ny);
                int pos = atomicAdd(&cnt_s, 1);
                if (pos < CAND_MAX)
                    keys[pos] = ((unsigned long long)__float_as_uint(planar) << 32) | (unsigned)i;
            }
        }
    }
    __syncthreads();
    int cnt = cnt_s;
    int ncand = min(cnt, CAND_MAX);
    int m = min(cnt, KMAX);

    // exact top-64 by (planar, idx) via rank-select (matches lax.top_k tie-break)
    for (int i = tid; i < ncand; i += 256) {
        unsigned long long ki = keys[i];
        int rank = 0;
        for (int j = 0; j < ncand; j++) rank += (keys[j] < ki) ? 1 : 0;
        if (rank < KMAX) selidx[rank] = (int)(ki & 0xffffffffu);
    }
    __syncthreads();

    if (tid < KMAX) {
        int k = tid;
        long base = (long)p * KMAX + k;
        if (k < m) {
            int i = selidx[k];
            float px = pts[i * 7], py = pts[i * 7 + 1], pz = pts[i * 7 + 2];
            float rx = px - cx, ry = py - cy, rz = pz - cz;
            float lx = __fadd_rn(__fmul_rn(rx, cth), __fmul_rn(ry, sth));
            float ly = __fsub_rn(__fmul_rn(ry, cth), __fmul_rn(rx, sth));
            float nx = lx / ddx, ny = ly / ddy, nz = rz / ddz - 0.5f;
            nl_s[k * 3] = nx; nl_s[k * 3 + 1] = ny; nl_s[k * 3 + 2] = nz;
            g_tok[base * 8 + 0] = nx; g_tok[base * 8 + 1] = ny; g_tok[base * 8 + 2] = nz;
            g_tok[base * 8 + 3] = pts[i * 7 + 3];
            g_tok[base * 8 + 4] = pts[i * 7 + 4];
            g_tok[base * 8 + 5] = pts[i * 7 + 5];
            g_tok[base * 8 + 6] = pts[i * 7 + 6];
            // projection
            float h0 = proj[0] * px + proj[1] * py + proj[2] * pz + proj[3];
            float h1 = proj[4] * px + proj[5] * py + proj[6] * pz + proj[7];
            float h2 = proj[8] * px + proj[9] * py + proj[10] * pz + proj[11];
            float depth = h2;
            float safe = (fabsf(depth) > 0.001f) ? depth : 0.001f;
            float rxx = 2.f * (h0 / safe) / 1279.f - 1.f;
            float ryy = 2.f * (h1 / safe) / 383.f - 1.f;
            int v = (depth > 0.1f) && (fabsf(rxx) <= 1.f) && (fabsf(ryy) <= 1.f);
            g_refs[base * 2] = rxx; g_refs[base * 2 + 1] = ryy;
            g_vm[base] = v ? 1.f : 0.f;
        } else {
            nl_s[k * 3] = nl_s[k * 3 + 1] = nl_s[k * 3 + 2] = 0.f;
            for (int j = 0; j < 8; j++) g_tok[base * 8 + j] = 0.f;
            g_refs[base * 2] = 0.f; g_refs[base * 2 + 1] = 0.f;
            g_vm[base] = 0.f;
        }
    }
    __syncthreads();

    const float INF = __int_as_float(0x7f800000);
    for (int e = tid; e < KMAX * KMAX; e += 256) {
        int i = e >> 6, j = e & 63;
        float v = INF;
        if (i < m && j < m) {
            float a = nl_s[i * 3] - nl_s[j * 3];
            float b = nl_s[i * 3 + 1] - nl_s[j * 3 + 1];
            float c = nl_s[i * 3 + 2] - nl_s[j * 3 + 2];
            v = sqrtf(a * a + b * b + c * c + 1e-12f);
        }
        dmat[e] = v;
    }
    __syncthreads();
    if (tid < KMAX && tid < m) {
        int k = tid;
        float b0 = INF, b1 = INF, b2 = INF, b3 = INF;
        for (int j = 0; j < m; j++) {
            float v = dmat[k * KMAX + j];
            if (v < b0)      { b3 = b2; b2 = b1; b1 = b0; b0 = v; }
            else if (v < b1) { b3 = b2; b2 = b1; b1 = v; }
            else if (v < b2) { b3 = b2; b2 = v; }
            else if (v < b3) { b3 = v; }
        }
        int mm = min(m, 4);
        float nb = 0.f;
        if (mm > 1) nb += b1;
        if (mm > 2) nb += b2;
        if (mm > 3) nb += b3;
        float nnb = (float)max(mm - 1, 1);
        g_tok[((long)p * KMAX + k) * 8 + 7] = expf(-nb / nnb);
    }
    if (tid == 0) { g_m[p] = m; out_counts[p] = (float)cnt; }
}

// ---------------- packed slot-GEMM: 2 channels x 4 slots, prepacked weights ----------------
// acc[i]   = (even-j sum, odd-j sum) channel 2c2,   local slot sl+i
// acc[4+i] = (even-j sum, odd-j sum) channel 2c2+1, local slot sl+i
__device__ __forceinline__ void jinit8(ull* acc, const float* __restrict__ B, int ch2) {
    float2 b = *(const float2*)&B[ch2];
    ull b0 = pack2f(b.x, 0.f), b1 = pack2f(b.y, 0.f);
#pragma unroll
    for (int i = 0; i < 4; i++) { acc[i] = b0; acc[4 + i] = b1; }
}

// accumulate A[sl..sl+3][0..255] @ W[0..255][2c2..2c2+1]; A is a chunk-local buffer
__device__ __forceinline__ void jgemm8(ull* acc, const float* A, int sl,
                                       const float4* __restrict__ PW, int c2) {
#pragma unroll 2
    for (int j4 = 0; j4 < HID / 4; j4++) {
        ulonglong2 w0 = *(const ulonglong2*)&PW[(2 * j4 + 0) * 128 + c2];
        ulonglong2 w1 = *(const ulonglong2*)&PW[(2 * j4 + 1) * 128 + c2];
#pragma unroll
        for (int i = 0; i < 4; i++) {
            ulonglong2 av = *(const ulonglong2*)&A[(sl + i) * HID + 4 * j4];
            acc[i]     = ffma2(av.x, w0.x, acc[i]);
            acc[i]     = ffma2(av.y, w1.x, acc[i]);
            acc[4 + i] = ffma2(av.x, w0.y, acc[4 + i]);
            acc[4 + i] = ffma2(av.y, w1.y, acc[4 + i]);
        }
    }
}

// MODE: 0 plain, 1 relu, 2 multiply-by-VM, 3 add-into-OUT.  OUT is chunk-local base.
template <int MODE>
__device__ __forceinline__ void jstore8(float* OUT, const ull* acc, int sl, int ch2,
                                        const float* VMp) {
#pragma unroll
    for (int i = 0; i < 4; i++) {
        float2 p0 = unpack2(acc[i]), p1 = unpack2(acc[4 + i]);
        float v0 = p0.x + p0.y, v1 = p1.x + p1.y;
        if (MODE == 1) { v0 = fmaxf(v0, 0.f); v1 = fmaxf(v1, 0.f); }
        if (MODE == 2) { float vm = VMp[sl + i]; v0 *= vm; v1 *= vm; }
        if (MODE == 3) {
            float2 e = *(const float2*)&OUT[(sl + i) * HID + ch2];
            v0 += e.x; v1 += e.y;
        }
        *(float2*)&OUT[(sl + i) * HID + ch2] = make_float2(v0, v1);
    }
}

// ---------------- kernel 3: persistent per-box MLP chain (512 thr, 2 CTA/SM) ----------------
__global__ void __launch_bounds__(512, 2) k_mlp(
    const float* __restrict__ pe_w1, const float* __restrict__ pe_b1,
    const float* __restrict__ pe_b2,
    const float* __restrict__ q_b,
    const float* __restrict__ off_w, const float* __restrict__ off_b,
    const float* __restrict__ wt_w,  const float* __restrict__ wt_b,
    const float* __restrict__ o_b1,
    const float* __restrict__ o_b2,
    const float* __restrict__ score_w, const float* __restrict__ score_b,
    float* __restrict__ out) {
    extern __shared__ float sm[];
    float* H   = sm;                 // 64*256 : h, fused in place
    float* B1  = H  + KMAX * HID;    // 16*256 : h1 -> q*vm -> o1 (chunk buffer)
    float* B2  = B1 + 16 * HID;      // 16*256 : context (chunk buffer)
    float* TOK = B2 + 16 * HID;      // 64*8
    float* REF = TOK + KMAX * 8;     // 64*2
    float* VMs = REF + KMAX * 2;     // 64
    float* OFS = VMs + KMAX;         // 64*8
    float* WTS = OFS + KMAX * 8;     // 64*4
    float* LG  = WTS + KMAX * 4;     // 64
    float* PW  = LG + KMAX;          // 64
    __shared__ int p_s;

    int tid = threadIdx.x;
    int d = tid & 255;              // output channel (scalar phases)
    int dh = tid >> 8;              // 0/1 slot-half for h1
    int warp = tid >> 5, lane = tid & 31;
    int c2 = tid & 127;             // channel-pair index
    int ch2 = c2 * 2;               // channel base
    int sl = (tid >> 7) * 4;        // local slot base for GEMMs (0,4,8,12)
    int kq = tid >> 6;              // 0..7 slot offset for sampling
    int cq = (tid & 63) << 2;       // float4 channel base for sampling

    while (true) {
        if (tid == 0) p_s = atomicAdd(&g_ctr, 1);
        __syncthreads();
        int p = p_s;
        if (p >= P_BOX) break;
        int m = g_m[p];
        if (m > 0) {
            int mt = (m + 15) & ~15;
            long base = (long)p * KMAX;

            for (int i = tid; i < mt * 8; i += 512) TOK[i] = g_tok[base * 8 + i];
            for (int i = tid; i < mt * 2; i += 512) REF[i] = g_refs[base * 2 + i];
            for (int i = tid; i < mt; i += 512) VMs[i] = g_vm[base + i];
            __syncthreads();

            for (int c0 = 0; c0 < mt; c0 += 16) {
                float* Hc = H + c0 * HID;

                // h1 = relu(tok @ pe_w1 + b1) -> B1 (chunk-local)
                {
                    float w[8];
#pragma unroll
                    for (int j = 0; j < 8; j++) w[j] = pe_w1[j * HID + d];
                    float b = pe_b1[d];
#pragma unroll
                    for (int i = 0; i < 8; i++) {
                        int kl = dh * 8 + i;
                        float a = b;
#pragma unroll
                        for (int j = 0; j < 8; j++) a = fmaf(TOK[(c0 + kl) * 8 + j], w[j], a);
                        B1[kl * HID + d] = fmaxf(a, 0.f);
                    }
                }
                __syncthreads();

                // h = h1 @ pe_w2 + b2 -> H[chunk]
                {
                    ull acc[8];
                    jinit8(acc, pe_b2, ch2);
                    jgemm8(acc, B1, sl, g_pw + PW_PE2, c2);
                    jstore8<0>(Hc, acc, sl, ch2, nullptr);
                }
                __syncthreads();

                // heads on chunk: one warp per slot (16 warps = 16 slots)
                {
                    int k = c0 + warp;
                    float po[12];
#pragma unroll
                    for (int i = 0; i < 12; i++) po[i] = 0.f;
                    for (int j = lane; j < HID; j += 32) {
                        float hv = H[k * HID + j];
#pragma unroll
                        for (int i = 0; i < 8; i++) po[i] = fmaf(hv, off_w[j * 8 + i], po[i]);
#pragma unroll
                        for (int i = 0; i < 4; i++) po[8 + i] = fmaf(hv, wt_w[j * 4 + i], po[8 + i]);
                    }
#pragma unroll
                    for (int i = 0; i < 12; i++) {
#pragma unroll
                        for (int o = 16; o > 0; o >>= 1) po[i] += __shfl_xor_sync(0xffffffffu, po[i], o);
                    }
                    if (lane == 0) {
#pragma unroll
                        for (int i = 0; i < 8; i++) OFS[k * 8 + i] = tanhf(po[i] + off_b[i]) * 0.04f;
                        float l0 = po[8] + wt_b[0], l1 = po[9] + wt_b[1];
                        float l2 = po[10] + wt_b[2], l3 = po[11] + wt_b[3];
                        float mx = fmaxf(fmaxf(l0, l1), fmaxf(l2, l3));
                        float e0 = expf(l0 - mx), e1 = expf(l1 - mx), e2 = expf(l2 - mx), e3 = expf(l3 - mx);
                        float inv = 1.f / (e0 + e1 + e2 + e3);
                        WTS[k * 4 + 0] = e0 * inv; WTS[k * 4 + 1] = e1 * inv;
                        WTS[k * 4 + 2] = e2 * inv; WTS[k * 4 + 3] = e3 * inv;
                    }
                }
                __syncthreads();

                // q*vm -> B1 (h1 dead; pe2 read finished 2 syncs ago)
                {
                    ull acc[8];
                    jinit8(acc, q_b, ch2);
                    jgemm8(acc, Hc, sl, g_pw + PW_QW, c2);
                    jstore8<2>(B1, acc, sl, ch2, VMs + c0);
                }

                // sampling -> B2 (chunk): thread covers 4 channels, 2 slots
#pragma unroll
                for (int k0 = 0; k0 < 16; k0 += 8) {
                    int kl = k0 + kq;
                    int k = c0 + kl;
                    float4 ctx = make_float4(0.f, 0.f, 0.f, 0.f);
                    if (VMs[k] != 0.f) {
                        float rx = REF[k * 2], ry = REF[k * 2 + 1];
#pragma unroll
                        for (int s2 = 0; s2 < 4; s2++) {
                            float gx = fminf(fmaxf(rx + OFS[k * 8 + s2 * 2 + 0], -1.2f), 1.2f);
                            float gy = fminf(fmaxf(ry + OFS[k * 8 + s2 * 2 + 1], -1.2f), 1.2f);
                            float px = (gx + 1.f) * 0.5f * (float)(WF - 1);
                            float py = (gy + 1.f) * 0.5f * (float)(HF - 1);
                            float x0f = floorf(px), y0f = floorf(py);
                            int x0 = (int)x0f, y0 = (int)y0f;
                            float wx = px - x0f, wy = py - y0f;
                            bool xin0 = (x0 >= 0) && (x0 < WF), xin1 = (x0 + 1 >= 0) && (x0 + 1 < WF);
                            bool yin0 = (y0 >= 0) && (y0 < HF), yin1 = (y0 + 1 >= 0) && (y0 + 1 < HF);
                            float4 s00 = make_float4(0.f, 0.f, 0.f, 0.f), s10 = s00, s01 = s00, s11 = s00;
                            if (xin0 && yin0) s00 = *(const float4*)&g_fm[(y0 * WF + x0) * HID + cq];
                            if (xin1 && yin0) s10 = *(const float4*)&g_fm[(y0 * WF + x0 + 1) * HID + cq];
                            if (xin0 && yin1) s01 = *(const float4*)&g_fm[((y0 + 1) * WF + x0) * HID + cq];
                            if (xin1 && yin1) s11 = *(const float4*)&g_fm[((y0 + 1) * WF + x0 + 1) * HID + cq];
                            float w00 = (1.f - wx) * (1.f - wy), w10 = wx * (1.f - wy);
                            float w01 = (1.f - wx) * wy,         w11 = wx * wy;
                            float ws = WTS[k * 4 + s2];
                            ctx.x += (s00.x * w00 + s10.x * w10 + s01.x * w01 + s11.x * w11) * ws;
                            ctx.y += (s00.y * w00 + s10.y * w10 + s01.y * w01 + s11.y * w11) * ws;
                            ctx.z += (s00.z * w00 + s10.z * w10 + s01.z * w01 + s11.z * w11) * ws;
                            ctx.w += (s00.w * w00 + s10.w * w10 + s01.w * w01 + s11.w * w11) * ws;
                        }
                    }
                    *(float4*)&B2[kl * HID + cq] = ctx;
                }
                __syncthreads();

                // o-MLP on chunk: o1 = relu([B1, B2] @ o_w1 + b1) -> overlay B1;
                // img_tok = o1 @ o_w2 + b2 ; H[chunk] += img_tok
                {
                    ull acc[8];
                    jinit8(acc, o_b1, ch2);
                    jgemm8(acc, B1, sl, g_pw + PW_OW1, c2);
                    jgemm8(acc, B2, sl, g_pw + PW_OW1 + 16384, c2);
                    __syncthreads();   // all B1/B2 reads done
                    jstore8<1>(B1, acc, sl, ch2, nullptr);
                    __syncthreads();   // o1 visible
                    ull acc2[8];
                    jinit8(acc2, o_b2, ch2);
                    jgemm8(acc2, B1, sl, g_pw + PW_OW2, c2);
                    jstore8<3>(Hc, acc2, sl, ch2, nullptr);
                }
                __syncthreads();   // B1/B2 free for next chunk
            }

            // logits (only valid slots)
            for (int k = warp; k < m; k += 16) {
                float pl = 0.f;
                for (int j = lane; j < HID; j += 32) pl = fmaf(H[k * HID + j], score_w[j], pl);
#pragma unroll
                for (int o = 16; o > 0; o >>= 1) pl += __shfl_xor_sync(0xffffffffu, pl, o);
                if (lane == 0) LG[k] = pl + score_b[0];
            }
            __syncthreads();

            // softmax over k<m (warp 0)
            if (tid < 32) {
                float mx = -3.4e38f;
                for (int k = tid; k < m; k += 32) mx = fmaxf(mx, LG[k]);
#pragma unroll
                for (int o = 16; o > 0; o >>= 1) mx = fmaxf(mx, __shfl_xor_sync(0xffffffffu, mx, o));
                float ssum = 0.f;
                for (int k = tid; k < m; k += 32) { float e = expf(LG[k] - mx); PW[k] = e; ssum += e; }
#pragma unroll
                for (int o = 16; o > 0; o >>= 1) ssum += __shfl_xor_sync(0xffffffffu, ssum, o);
                float inv = 1.f / ssum;
                for (int k = tid; k < m; k += 32) PW[k] *= inv;
            }
            __syncthreads();

            if (tid < 256) {
                float pooled = 0.f;
                for (int k = 0; k < m; k++) pooled = fmaf(PW[k], H[k * HID + tid], pooled);
                out[p * HID + tid] = pooled;
            }
        } else {
            if (tid < 256) out[p * HID + tid] = 0.f;
        }
        __syncthreads();  // protect smem reuse + p_s for next iteration
    }
}

// ---------------- launcher ----------------
extern "C" void kernel_launch(void* const* d_in, const int* in_sizes, int n_in,
                              void* d_out, int out_size) {
    const float* points  = (const float*)d_in[0];
    const float* boxes   = (const float*)d_in[1];
    const float* img     = (const float*)d_in[2];
    const float* proj    = (const float*)d_in[3];
    const float* pe_w1   = (const float*)d_in[4];
    const float* pe_b1   = (const float*)d_in[5];
    const float* pe_w2   = (const float*)d_in[6];
    const float* pe_b2   = (const float*)d_in[7];
    const float* q_w     = (const float*)d_in[8];
    const float* q_b     = (const float*)d_in[9];
    const float* f_w     = (const float*)d_in[10];
    const float* f_b     = (const float*)d_in[11];
    const float* off_w   = (const float*)d_in[12];
    const float* off_b   = (const float*)d_in[13];
    const float* wt_w    = (const float*)d_in[14];
    const float* wt_b    = (const float*)d_in[15];
    const float* o_w1    = (const float*)d_in[16];
    const float* o_b1    = (const float*)d_in[17];
    const float* o_w2    = (const float*)d_in[18];
    const float* o_b2    = (const float*)d_in[19];
    const float* score_w = (const float*)d_in[20];
    const float* score_b = (const float*)d_in[21];
    float* out = (float*)d_out;

    static cudaStream_t s2 = nullptr;
    static cudaEvent_t ev_fork = nullptr, ev_join = nullptr;
    if (s2 == nullptr) {
        cudaStreamCreateWithFlags(&s2, cudaStreamNonBlocking);
        cudaEventCreateWithFlags(&ev_fork, cudaEventDisableTiming);
        cudaEventCreateWithFlags(&ev_join, cudaEventDisableTiming);
    }

    const int smem_fm  = (C_IMG * HID + C_IMG * FM_PIX) * 4;                 // 110592
    const int smem_mlp = (KMAX * HID + 2 * 16 * HID + KMAX * 8 + KMAX * 2 +
                          KMAX + KMAX * 8 + KMAX * 4 + KMAX + KMAX) * 4;    // 104704

    cudaFuncSetAttribute(k_fm,  cudaFuncAttributeMaxDynamicSharedMemorySize, smem_fm);
    cudaFuncSetAttribute(k_mlp, cudaFuncAttributeMaxDynamicSharedMemorySize, smem_mlp);

    // fork: wpack + k_fm (persistent) on s2, prep+sel on default stream, join before k_mlp
    cudaEventRecord(ev_fork, 0);
    cudaStreamWaitEvent(s2, ev_fork, 0);
    k_wpack_all<<<640, 128, 0, s2>>>(pe_w2, q_w, o_w1, o_w2);
    k_fm<<<FM_GRID, 256, smem_fm, s2>>>(img, f_w, f_b);
    cudaEventRecord(ev_join, s2);

    k_prep<<<(N_PTS + 255) / 256, 256>>>(points);
    k_sel<<<P_BOX, 256>>>(points, boxes, proj, out + P_BOX * HID);

    cudaStreamWaitEvent(0, ev_join, 0);
    k_mlp<<<304, 512, smem_mlp>>>(pe_w1, pe_b1, pe_b2, q_b,
                                  off_w, off_b, wt_w, wt_b, o_b1,
                                  o_b2, score_w, score_b, out);
}

// round 16
// speedup vs baseline: 1.3278x; 1.3278x over previous
#include <cuda_runtime.h>

#define P_BOX 512
#define N_PTS 50000
#define KMAX 64
#define HID 256
#define C_IMG 96
#define HF 160
#define WF 512
#define NPIX (HF*WF)
#define CAND_MAX 2048
#define FM_PIX 32
#define FM_GRID 304

typedef unsigned long long ull;

// ---------------- device scratch (no allocations allowed) ----------------
__device__ float g_fm[NPIX * HID];          // (H*W, 256) pixel-major
__device__ float g_tok[P_BOX * KMAX * 8];   // tokens
__device__ float g_refs[P_BOX * KMAX * 2];  // rx, ry
__device__ float g_vm[P_BOX * KMAX];        // projection-valid mask (0/1)
__device__ int   g_m[P_BOX];                // min(counts, 64)
__device__ float2 g_xy[N_PTS];              // SoA xy
__device__ float  g_z[N_PTS];               // SoA z
__device__ int   g_ctr;                     // persistent work counter
// packed weights, channel-pair layout:
//   g_pw[seg + j2*128 + c2] = (W[2j2][2c2], W[2j2+1][2c2], W[2j2][2c2+1], W[2j2+1][2c2+1])
// ulonglong2 view: .x = packed (row-pair) for channel 2c2, .y = for channel 2c2+1
__device__ float4 g_pw[81920];
#define PW_PE2 0
#define PW_QW  16384
#define PW_OW1 32768
#define PW_OW2 65536

#define BARG(tg) asm volatile("bar.sync %0, 256;" :: "r"((tg) + 1) : "memory")

// ---------------- f32x2 packed helpers ----------------
__device__ __forceinline__ ull ffma2(ull a, ull b, ull c) {
    ull d; asm("fma.rn.f32x2 %0, %1, %2, %3;" : "=l"(d) : "l"(a), "l"(b), "l"(c)); return d;
}
__device__ __forceinline__ ull pack2f(float x, float y) {
    ull d; asm("mov.b64 %0, {%1, %2};" : "=l"(d) : "f"(x), "f"(y)); return d;
}
__device__ __forceinline__ ull packdup(float x) {
    ull d; asm("mov.b64 %0, {%1, %1};" : "=l"(d) : "f"(x)); return d;
}
__device__ __forceinline__ float2 unpack2(ull v) {
    float2 r; asm("mov.b64 {%0, %1}, %2;" : "=f"(r.x), "=f"(r.y) : "l"(v)); return r;
}

// ---------------- kernel 0: AoS -> SoA prep + counter reset ----------------
__global__ void __launch_bounds__(256) k_prep(const float* __restrict__ pts) {
    int i = blockIdx.x * 256 + threadIdx.x;
    if (i == 0) g_ctr = 0;
    if (i < N_PTS) {
        g_xy[i] = make_float2(pts[i * 7], pts[i * 7 + 1]);
        g_z[i] = pts[i * 7 + 2];
    }
}

// ---------------- kernel 0b: all weight packing in ONE launch ----------------
__global__ void __launch_bounds__(128) k_wpack_all(const float* __restrict__ pe_w2,
                                                   const float* __restrict__ q_w,
                                                   const float* __restrict__ o_w1,
                                                   const float* __restrict__ o_w2) {
    int b = blockIdx.x, c2 = threadIdx.x;
    const float* W; int off, j2;
    if (b < 128)      { W = pe_w2; off = PW_PE2; j2 = b; }
    else if (b < 256) { W = q_w;   off = PW_QW;  j2 = b - 128; }
    else if (b < 512) { W = o_w1;  off = PW_OW1; j2 = b - 256; }
    else              { W = o_w2;  off = PW_OW2; j2 = b - 512; }
    const float* r0 = W + (2 * j2) * HID + 2 * c2;
    const float* r1 = W + (2 * j2 + 1) * HID + 2 * c2;
    g_pw[off + j2 * 128 + c2] = make_float4(r0[0], r1[0], r0[1], r1[1]);
}

// ---------------- kernel 1: fm = img^T @ f_w + f_b (persistent, f32x2) ----------------
__global__ void __launch_bounds__(256, 2) k_fm(const float* __restrict__ img,
                                               const float* __restrict__ fw,
                                               const float* __restrict__ fb) {
    extern __shared__ float smf[];
    float* w_s = smf;                 // 96*256, loaded once
    float* a_s = smf + C_IMG * HID;   // 96*FM_PIX, layout [c][pi], reloaded per tile
    int tid = threadIdx.x;
    for (int i = tid; i < C_IMG * HID; i += 256) w_s[i] = fw[i];
    float b = fb[tid];
    ull bb = pack2f(b, b);

    for (int t = blockIdx.x; t < NPIX / FM_PIX; t += FM_GRID) {
        int p0 = t * FM_PIX;
        __syncthreads();   // previous tile's a_s readers done (also covers w_s load on iter 0)
        for (int i = tid; i < C_IMG * FM_PIX; i += 256) {
            int c = i / FM_PIX, pi = i - c * FM_PIX;
            a_s[c * FM_PIX + pi] = img[c * NPIX + p0 + pi];
        }
        __syncthreads();
        ull acc[FM_PIX / 2];   // pixel pairs
#pragma unroll
        for (int i = 0; i < FM_PIX / 2; i++) acc[i] = bb;
#pragma unroll 4
        for (int c = 0; c < C_IMG; c++) {
            ull wd = packdup(w_s[c * HID + tid]);
            const ulonglong2* ap = (const ulonglong2*)&a_s[c * FM_PIX];
#pragma unroll
            for (int q = 0; q < FM_PIX / 4; q++) {
                ulonglong2 av = ap[q];
                acc[2 * q + 0] = ffma2(av.x, wd, acc[2 * q + 0]);
                acc[2 * q + 1] = ffma2(av.y, wd, acc[2 * q + 1]);
            }
        }
#pragma unroll
        for (int i = 0; i < FM_PIX / 2; i++) {
            float2 r = unpack2(acc[i]);
            g_fm[(p0 + 2 * i + 0) * HID + tid] = r.x;
            g_fm[(p0 + 2 * i + 1) * HID + tid] = r.y;
        }
    }
}

// ---------------- kernel 2: per-box selection + knn/density + projection ----------------
__global__ void __launch_bounds__(256) k_sel(const float* __restrict__ pts,
                                             const float* __restrict__ boxes,
                                             const float* __restrict__ proj,
                                             float* __restrict__ out_counts) {
    __shared__ unsigned long long keys[CAND_MAX];
    __shared__ int cnt_s;
    __shared__ int selidx[KMAX];
    __shared__ float nl_s[KMAX * 3];
    __shared__ float dmat[KMAX * KMAX];

    int p = blockIdx.x, tid = threadIdx.x;
    if (tid == 0) cnt_s = 0;
    __syncthreads();

    float cx = boxes[p * 7 + 0], cy = boxes[p * 7 + 1], cz = boxes[p * 7 + 2];
    float dx = boxes[p * 7 + 3], dy = boxes[p * 7 + 4], dz = boxes[p * 7 + 5];
    float yaw = boxes[p * 7 + 6];
    float cth = cosf(yaw), sth = sinf(yaw);
    float hx = dx * 0.5f, hy = dy * 0.5f, hz = dz * 0.5f;
    float ddx = fmaxf(dx, 0.001f), ddy = fmaxf(dy, 0.001f), ddz = fmaxf(dz, 0.001f);

    // scan with 4-way ILP: front-batch 4 independent xy loads per iteration
#pragma unroll 4
    for (int i = tid; i < N_PTS; i += 256) {
        float2 xy = g_xy[i];
        float rx = xy.x - cx, ry = xy.y - cy;
        // explicit non-fused mul/add to track the reference's boundary decisions
        float lx = __fadd_rn(__fmul_rn(rx, cth), __fmul_rn(ry, sth));
        float ly = __fsub_rn(__fmul_rn(ry, cth), __fmul_rn(rx, sth));
        if (fabsf(lx) <= hx && fabsf(ly) <= hy) {
            float rz = g_z[i] - cz;
            if (fabsf(rz) <= hz) {
                float nx = lx / ddx, ny = ly / ddy;
                float planar = sqrtf(nx * nx + ny * ny);
                int pos = atomicAdd(&cnt_s, 1);
                if (pos < CAND_MAX)
                    keys[pos] = ((unsigned long long)__float_as_uint(planar) << 32) | (unsigned)i;
            }
        }
    }
    __syncthreads();
    int cnt = cnt_s;
    int ncand = min(cnt, CAND_MAX);
    int m = min(cnt, KMAX);

    // exact top-64 by (planar, idx) via rank-select (matches lax.top_k tie-break)
    for (int i = tid; i < ncand; i += 256) {
        unsigned long long ki = keys[i];
        int rank = 0;
        for (int j = 0; j < ncand; j++) rank += (keys[j] < ki) ? 1 : 0;
        if (rank < KMAX) selidx[rank] = (int)(ki & 0xffffffffu);
    }
    __syncthreads();

    if (tid < KMAX) {
        int k = tid;
        long base = (long)p * KMAX + k;
        if (k < m) {
            int i = selidx[k];
            float px = pts[i * 7], py = pts[i * 7 + 1], pz = pts[i * 7 + 2];
            float rx = px - cx, ry = py - cy, rz = pz - cz;
            float lx = __fadd_rn(__fmul_rn(rx, cth), __fmul_rn(ry, sth));
            float ly = __fsub_rn(__fmul_rn(ry, cth), __fmul_rn(rx, sth));
            float nx = lx / ddx, ny = ly / ddy, nz = rz / ddz - 0.5f;
            nl_s[k * 3] = nx; nl_s[k * 3 + 1] = ny; nl_s[k * 3 + 2] = nz;
            g_tok[base * 8 + 0] = nx; g_tok[base * 8 + 1] = ny; g_tok[base * 8 + 2] = nz;
            g_tok[base * 8 + 3] = pts[i * 7 + 3];
            g_tok[base * 8 + 4] = pts[i * 7 + 4];
            g_tok[base * 8 + 5] = pts[i * 7 + 5];
            g_tok[base * 8 + 6] = pts[i * 7 + 6];
            // projection
            float h0 = proj[0] * px + proj[1] * py + proj[2] * pz + proj[3];
            float h1 = proj[4] * px + proj[5] * py + proj[6] * pz + proj[7];
            float h2 = proj[8] * px + proj[9] * py + proj[10] * pz + proj[11];
            float depth = h2;
            float safe = (fabsf(depth) > 0.001f) ? depth : 0.001f;
            float rxx = 2.f * (h0 / safe) / 1279.f - 1.f;
            float ryy = 2.f * (h1 / safe) / 383.f - 1.f;
            int v = (depth > 0.1f) && (fabsf(rxx) <= 1.f) && (fabsf(ryy) <= 1.f);
            g_refs[base * 2] = rxx; g_refs[base * 2 + 1] = ryy;
            g_vm[base] = v ? 1.f : 0.f;
        } else {
            nl_s[k * 3] = nl_s[k * 3 + 1] = nl_s[k * 3 + 2] = 0.f;
            for (int j = 0; j < 8; j++) g_tok[base * 8 + j] = 0.f;
            g_refs[base * 2] = 0.f; g_refs[base * 2 + 1] = 0.f;
            g_vm[base] = 0.f;
        }
    }
    __syncthreads();

    const float INF = __int_as_float(0x7f800000);
    for (int e = tid; e < KMAX * KMAX; e += 256) {
        int i = e >> 6, j = e & 63;
        float v = INF;
        if (i < m && j < m) {
            float a = nl_s[i * 3] - nl_s[j * 3];
            float b = nl_s[i * 3 + 1] - nl_s[j * 3 + 1];
            float c = nl_s[i * 3 + 2] - nl_s[j * 3 + 2];
            v = sqrtf(a * a + b * b + c * c + 1e-12f);
        }
        dmat[e] = v;
    }
    __syncthreads();
    if (tid < KMAX && tid < m) {
        int k = tid;
        float b0 = INF, b1 = INF, b2 = INF, b3 = INF;
        for (int j = 0; j < m; j++) {
            float v = dmat[k * KMAX + j];
            if (v < b0)      { b3 = b2; b2 = b1; b1 = b0; b0 = v; }
            else if (v < b1) { b3 = b2; b2 = b1; b1 = v; }
            else if (v < b2) { b3 = b2; b2 = v; }
            else if (v < b3) { b3 = v; }
        }
        int mm = min(m, 4);
        float nb = 0.f;
        if (mm > 1) nb += b1;
        if (mm > 2) nb += b2;
        if (mm > 3) nb += b3;
        float nnb = (float)max(mm - 1, 1);
        g_tok[((long)p * KMAX + k) * 8 + 7] = expf(-nb / nnb);
    }
    if (tid == 0) { g_m[p] = m; out_counts[p] = (float)cnt; }
}

// ---------------- packed slot-GEMM: 2 channels x 8 slots, prepacked weights ----------------
// acc[i]   = (even-j sum, odd-j sum) channel 2c2,   slot s0+i
// acc[8+i] = (even-j sum, odd-j sum) channel 2c2+1, slot s0+i
__device__ __forceinline__ void jacc2_init(ull* acc, const float* __restrict__ B, int ch2) {
    float2 b = *(const float2*)&B[ch2];
    ull b0 = pack2f(b.x, 0.f), b1 = pack2f(b.y, 0.f);
#pragma unroll
    for (int i = 0; i < 8; i++) { acc[i] = b0; acc[8 + i] = b1; }
}

__device__ __forceinline__ void jacc2_gemm(ull* acc, const float* A,
                                           const float4* __restrict__ PW, int s0, int c2) {
#pragma unroll 2
    for (int j4 = 0; j4 < HID / 4; j4++) {
        // rows 4j4,4j4+1 and 4j4+2,4j4+3, both channels, pre-packed
        ulonglong2 w0 = *(const ulonglong2*)&PW[(2 * j4 + 0) * 128 + c2];
        ulonglong2 w1 = *(const ulonglong2*)&PW[(2 * j4 + 1) * 128 + c2];
#pragma unroll
        for (int i = 0; i < 8; i++) {
            ulonglong2 av = *(const ulonglong2*)&A[(s0 + i) * HID + 4 * j4];
            acc[i]     = ffma2(av.x, w0.x, acc[i]);
            acc[i]     = ffma2(av.y, w1.x, acc[i]);
            acc[8 + i] = ffma2(av.x, w0.y, acc[8 + i]);
            acc[8 + i] = ffma2(av.y, w1.y, acc[8 + i]);
        }
    }
}

// MODE: 0 plain, 1 relu, 2 multiply-by-VM, 3 add-into-OUT
template <int MODE>
__device__ __forceinline__ void jacc2_store(float* OUT, const ull* acc, int s0, int ch2,
                                            const float* VMp) {
#pragma unroll
    for (int i = 0; i < 8; i++) {
        float2 p0 = unpack2(acc[i]), p1 = unpack2(acc[8 + i]);
        float v0 = p0.x + p0.y, v1 = p1.x + p1.y;
        if (MODE == 1) { v0 = fmaxf(v0, 0.f); v1 = fmaxf(v1, 0.f); }
        if (MODE == 2) { float vm = VMp[s0 + i]; v0 *= vm; v1 *= vm; }
        if (MODE == 3) {
            float2 e = *(const float2*)&OUT[(s0 + i) * HID + ch2];
            v0 += e.x; v1 += e.y;
        }
        *(float2*)&OUT[(s0 + i) * HID + ch2] = make_float2(v0, v1);
    }
}

// ---------------- kernel 3: persistent per-box MLP chain (512 threads) ----------------
__global__ void __launch_bounds__(512, 1) k_mlp(
    const float* __restrict__ pe_w1, const float* __restrict__ pe_b1,
    const float* __restrict__ pe_b2,
    const float* __restrict__ q_b,
    const float* __restrict__ off_w, const float* __restrict__ off_b,
    const float* __restrict__ wt_w,  const float* __restrict__ wt_b,
    const float* __restrict__ o_b1,
    const float* __restrict__ o_b2,
    const float* __restrict__ score_w, const float* __restrict__ score_b,
    float* __restrict__ out) {
    extern __shared__ float sm[];
    float* H   = sm;                 // 64*256 : h, later fused (in place)
    float* Q   = H  + KMAX * HID;    // 64*256 : h1, later q*vm
    float* CX  = Q  + KMAX * HID;    // 64*256 : context, o1 overlay per tile
    float* TOK = CX + KMAX * HID;    // 64*8
    float* REF = TOK + KMAX * 8;     // 64*2
    float* VMs = REF + KMAX * 2;     // 64
    float* OFS = VMs + KMAX;         // 64*8
    float* WTS = OFS + KMAX * 8;     // 64*4
    float* LG  = WTS + KMAX * 4;     // 64
    float* PW  = LG + KMAX;          // 64
    __shared__ int p_s;

    int tid = threadIdx.x;
    int d = tid & 255;        // output channel (scalar phases)
    int tg = tid >> 8;        // tile group 0/1
    int warp = tid >> 5, lane = tid & 31;
    int half = (tid >> 7) & 1;      // slot-half within group
    int c2 = tid & 127;             // channel-pair index
    int ch2 = c2 * 2;               // channel base

    while (true) {
        if (tid == 0) p_s = atomicAdd(&g_ctr, 1);
        __syncthreads();
        int p = p_s;
        if (p >= P_BOX) break;
        int m = g_m[p];
        if (m > 0) {
            int mt = (m + 15) & ~15;
            long base = (long)p * KMAX;

            for (int i = tid; i < mt * 8; i += 512) TOK[i] = g_tok[base * 8 + i];
            for (int i = tid; i < mt * 2; i += 512) REF[i] = g_refs[base * 2 + i];
            for (int i = tid; i < mt; i += 512) VMs[i] = g_vm[base + i];
            __syncthreads();

            // h1 = relu(tok @ pe_w1 + b1) -> Q   (each group does alternate slots)
            {
                float w[8];
#pragma unroll
                for (int j = 0; j < 8; j++) w[j] = pe_w1[j * HID + d];
                float b = pe_b1[d];
                for (int k = tg; k < mt; k += 2) {
                    float acc = b;
#pragma unroll
                    for (int j = 0; j < 8; j++) acc = fmaf(TOK[k * 8 + j], w[j], acc);
                    Q[k * HID + d] = fmaxf(acc, 0.f);
                }
            }
            __syncthreads();

            // h = h1 @ pe_w2 + b2 -> H
            for (int k0 = tg * 16; k0 < mt; k0 += 32) {
                int s0 = k0 + half * 8;
                ull acc[16];
                jacc2_init(acc, pe_b2, ch2);
                jacc2_gemm(acc, Q, g_pw + PW_PE2, s0, c2);
                jacc2_store<0>(H, acc, s0, ch2, nullptr);
            }
            __syncthreads();

            // heads: offs = tanh(h@off_w+off_b)*0.04 ; wts = softmax(h@wt_w+wt_b)
            for (int k = warp; k < mt; k += 16) {
                float po[12];
#pragma unroll
                for (int i = 0; i < 12; i++) po[i] = 0.f;
                for (int j = lane; j < HID; j += 32) {
                    float hv = H[k * HID + j];
#pragma unroll
                    for (int i = 0; i < 8; i++) po[i] = fmaf(hv, off_w[j * 8 + i], po[i]);
#pragma unroll
                    for (int i = 0; i < 4; i++) po[8 + i] = fmaf(hv, wt_w[j * 4 + i], po[8 + i]);
                }
#pragma unroll
                for (int i = 0; i < 12; i++) {
#pragma unroll
                    for (int o = 16; o > 0; o >>= 1) po[i] += __shfl_xor_sync(0xffffffffu, po[i], o);
                }
                if (lane == 0) {
#pragma unroll
                    for (int i = 0; i < 8; i++) OFS[k * 8 + i] = tanhf(po[i] + off_b[i]) * 0.04f;
                    float l0 = po[8] + wt_b[0], l1 = po[9] + wt_b[1];
                    float l2 = po[10] + wt_b[2], l3 = po[11] + wt_b[3];
                    float mx = fmaxf(fmaxf(l0, l1), fmaxf(l2, l3));
                    float e0 = expf(l0 - mx), e1 = expf(l1 - mx), e2 = expf(l2 - mx), e3 = expf(l3 - mx);
                    float inv = 1.f / (e0 + e1 + e2 + e3);
                    WTS[k * 4 + 0] = e0 * inv; WTS[k * 4 + 1] = e1 * inv;
                    WTS[k * 4 + 2] = e2 * inv; WTS[k * 4 + 3] = e3 * inv;
                }
            }
            __syncthreads();

            // q*vm -> Q (h1 dead)
            for (int k0 = tg * 16; k0 < mt; k0 += 32) {
                int s0 = k0 + half * 8;
                ull acc[16];
                jacc2_init(acc, q_b, ch2);
                jacc2_gemm(acc, H, g_pw + PW_QW, s0, c2);
                jacc2_store<2>(Q, acc, s0, ch2, VMs);
            }

            // sampling -> CX: thread covers 4 channels, 8 slots per pass
            {
                int kq = tid >> 6;          // 0..7 slot offset
                int cq = (tid & 63) << 2;   // channel base (float4)
                for (int k0 = 0; k0 < mt; k0 += 8) {
                    int k = k0 + kq;
                    float4 ctx = make_float4(0.f, 0.f, 0.f, 0.f);
                    if (VMs[k] != 0.f) {
                        float rx = REF[k * 2], ry = REF[k * 2 + 1];
#pragma unroll
                        for (int s2 = 0; s2 < 4; s2++) {
                            float gx = fminf(fmaxf(rx + OFS[k * 8 + s2 * 2 + 0], -1.2f), 1.2f);
                            float gy = fminf(fmaxf(ry + OFS[k * 8 + s2 * 2 + 1], -1.2f), 1.2f);
                            float px = (gx + 1.f) * 0.5f * (float)(WF - 1);
                            float py = (gy + 1.f) * 0.5f * (float)(HF - 1);
                            float x0f = floorf(px), y0f = floorf(py);
                            int x0 = (int)x0f, y0 = (int)y0f;
                            float wx = px - x0f, wy = py - y0f;
                            bool xin0 = (x0 >= 0) && (x0 < WF), xin1 = (x0 + 1 >= 0) && (x0 + 1 < WF);
                            bool yin0 = (y0 >= 0) && (y0 < HF), yin1 = (y0 + 1 >= 0) && (y0 + 1 < HF);
                            float4 s00 = make_float4(0.f, 0.f, 0.f, 0.f), s10 = s00, s01 = s00, s11 = s00;
                            if (xin0 && yin0) s00 = *(const float4*)&g_fm[(y0 * WF + x0) * HID + cq];
                            if (xin1 && yin0) s10 = *(const float4*)&g_fm[(y0 * WF + x0 + 1) * HID + cq];
                            if (xin0 && yin1) s01 = *(const float4*)&g_fm[((y0 + 1) * WF + x0) * HID + cq];
                            if (xin1 && yin1) s11 = *(const float4*)&g_fm[((y0 + 1) * WF + x0 + 1) * HID + cq];
                            float w00 = (1.f - wx) * (1.f - wy), w10 = wx * (1.f - wy);
                            float w01 = (1.f - wx) * wy,         w11 = wx * wy;
                            float ws = WTS[k * 4 + s2];
                            ctx.x += (s00.x * w00 + s10.x * w10 + s01.x * w01 + s11.x * w11) * ws;
                            ctx.y += (s00.y * w00 + s10.y * w10 + s01.y * w01 + s11.y * w11) * ws;
                            ctx.z += (s00.z * w00 + s10.z * w10 + s01.z * w01 + s11.z * w11) * ws;
                            ctx.w += (s00.w * w00 + s10.w * w10 + s01.w * w01 + s11.w * w11) * ws;
                        }
                    }
                    *(float4*)&CX[k * HID + cq] = ctx;
                }
            }
            __syncthreads();

            // o-MLP per 16-slot tile (group-local, named barriers):
            // o1 = relu([q*vm, ctx] @ o_w1 + b1)  stored over the dead CX tile
            // img_tok = o1 @ o_w2 + b2 ; fused = h + img_tok (in place on H)
            for (int k0 = tg * 16; k0 < mt; k0 += 32) {
                int s0 = k0 + half * 8;
                ull acc[16];
                jacc2_init(acc, o_b1, ch2);
                jacc2_gemm(acc, Q, g_pw + PW_OW1, s0, c2);
                jacc2_gemm(acc, CX, g_pw + PW_OW1 + 16384, s0, c2);
                BARG(tg);   // group's CX-tile reads done
                jacc2_store<1>(CX, acc, s0, ch2, nullptr);
                BARG(tg);   // o1 visible to group
                ull acc2[16];
                jacc2_init(acc2, o_b2, ch2);
                jacc2_gemm(acc2, CX, g_pw + PW_OW2, s0, c2);
                jacc2_store<3>(H, acc2, s0, ch2, nullptr);
            }
            __syncthreads();

            // logits (only valid slots)
            for (int k = warp; k < m; k += 16) {
                float pl = 0.f;
                for (int j = lane; j < HID; j += 32) pl = fmaf(H[k * HID + j], score_w[j], pl);
#pragma unroll
                for (int o = 16; o > 0; o >>= 1) pl += __shfl_xor_sync(0xffffffffu, pl, o);
                if (lane == 0) LG[k] = pl + score_b[0];
            }
            __syncthreads();

            // softmax over k<m (warp 0)
            if (tid < 32) {
                float mx = -3.4e38f;
                for (int k = tid; k < m; k += 32) mx = fmaxf(mx, LG[k]);
#pragma unroll
                for (int o = 16; o > 0; o >>= 1) mx = fmaxf(mx, __shfl_xor_sync(0xffffffffu, mx, o));
                float ssum = 0.f;
                for (int k = tid; k < m; k += 32) { float e = expf(LG[k] - mx); PW[k] = e; ssum += e; }
#pragma unroll
                for (int o = 16; o > 0; o >>= 1) ssum += __shfl_xor_sync(0xffffffffu, ssum, o);
                float inv = 1.f / ssum;
                for (int k = tid; k < m; k += 32) PW[k] *= inv;
            }
            __syncthreads();

            if (tid < 256) {
                float pooled = 0.f;
                for (int k = 0; k < m; k++) pooled = fmaf(PW[k], H[k * HID + tid], pooled);
                out[p * HID + tid] = pooled;
            }
        } else {
            if (tid < 256) out[p * HID + tid] = 0.f;
        }
        __syncthreads();  // protect smem reuse + p_s for next iteration
    }
}

// ---------------- launcher ----------------
extern "C" void kernel_launch(void* const* d_in, const int* in_sizes, int n_in,
                              void* d_out, int out_size) {
    const float* points  = (const float*)d_in[0];
    const float* boxes   = (const float*)d_in[1];
    const float* img     = (const float*)d_in[2];
    const float* proj    = (const float*)d_in[3];
    const float* pe_w1   = (const float*)d_in[4];
    const float* pe_b1   = (const float*)d_in[5];
    const float* pe_w2   = (const float*)d_in[6];
    const float* pe_b2   = (const float*)d_in[7];
    const float* q_w     = (const float*)d_in[8];
    const float* q_b     = (const float*)d_in[9];
    const float* f_w     = (const float*)d_in[10];
    const float* f_b     = (const float*)d_in[11];
    const float* off_w   = (const float*)d_in[12];
    const float* off_b   = (const float*)d_in[13];
    const float* wt_w    = (const float*)d_in[14];
    const float* wt_b    = (const float*)d_in[15];
    const float* o_w1    = (const float*)d_in[16];
    const float* o_b1    = (const float*)d_in[17];
    const float* o_w2    = (const float*)d_in[18];
    const float* o_b2    = (const float*)d_in[19];
    const float* score_w = (const float*)d_in[20];
    const float* score_b = (const float*)d_in[21];
    float* out = (float*)d_out;

    static cudaStream_t s2 = nullptr;
    static cudaEvent_t ev_fork = nullptr, ev_join = nullptr;
    if (s2 == nullptr) {
        cudaStreamCreateWithFlags(&s2, cudaStreamNonBlocking);
        cudaEventCreateWithFlags(&ev_fork, cudaEventDisableTiming);
        cudaEventCreateWithFlags(&ev_join, cudaEventDisableTiming);
    }

    const int smem_fm  = (C_IMG * HID + C_IMG * FM_PIX) * 4;                 // 110592
    const int smem_mlp = (3 * KMAX * HID + KMAX * 8 + KMAX * 2 +
                          KMAX + KMAX * 8 + KMAX * 4 + KMAX + KMAX) * 4;    // 203008

    cudaFuncSetAttribute(k_fm,  cudaFuncAttributeMaxDynamicSharedMemorySize, smem_fm);
    cudaFuncSetAttribute(k_mlp, cudaFuncAttributeMaxDynamicSharedMemorySize, smem_mlp);

    // fork: wpack + k_fm (persistent) on s2, prep+sel on default stream, join before k_mlp
    cudaEventRecord(ev_fork, 0);
    cudaStreamWaitEvent(s2, ev_fork, 0);
    k_wpack_all<<<640, 128, 0, s2>>>(pe_w2, q_w, o_w1, o_w2);
    k_fm<<<FM_GRID, 256, smem_fm, s2>>>(img, f_w, f_b);
    cudaEventRecord(ev_join, s2);

    k_prep<<<(N_PTS + 255) / 256, 256>>>(points);
    k_sel<<<P_BOX, 256>>>(points, boxes, proj, out + P_BOX * HID);

    cudaStreamWaitEvent(0, ev_join, 0);
    k_mlp<<<152, 512, smem_mlp>>>(pe_w1, pe_b1, pe_b2, q_b,
                                  off_w, off_b, wt_w, wt_b, o_b1,
                                  o_b2, score_w, score_b, out);
}

// round 17
// speedup vs baseline: 1.3694x; 1.0313x over previous
#include <cuda_runtime.h>

#define P_BOX 512
#define N_PTS 50000
#define KMAX 64
#define HID 256
#define C_IMG 96
#define HF 160
#define WF 512
#define NPIX (HF*WF)
#define CAND_MAX 2048
#define FM_PIX 32
#define FM_GRID 304

typedef unsigned long long ull;

// ---------------- device scratch (no allocations allowed) ----------------
__device__ float g_fm[NPIX * HID];          // (H*W, 256) pixel-major
__device__ float g_tok[P_BOX * KMAX * 8];   // tokens
__device__ float g_refs[P_BOX * KMAX * 2];  // rx, ry
__device__ float g_vm[P_BOX * KMAX];        // projection-valid mask (0/1)
__device__ int   g_m[P_BOX];                // min(counts, 64)
__device__ float2 g_xy[N_PTS];              // SoA xy
__device__ float  g_z[N_PTS];               // SoA z
__device__ int   g_ctr;                     // persistent work counter
// packed weights, channel-pair layout:
//   g_pw[seg + j2*128 + c2] = (W[2j2][2c2], W[2j2+1][2c2], W[2j2][2c2+1], W[2j2+1][2c2+1])
// ulonglong2 view: .x = packed (row-pair) for channel 2c2, .y = for channel 2c2+1
__device__ float4 g_pw[81920];
#define PW_PE2 0
#define PW_QW  16384
#define PW_OW1 32768
#define PW_OW2 65536

#define BARG(tg) asm volatile("bar.sync %0, 256;" :: "r"((tg) + 1) : "memory")

// ---------------- f32x2 packed helpers ----------------
__device__ __forceinline__ ull ffma2(ull a, ull b, ull c) {
    ull d; asm("fma.rn.f32x2 %0, %1, %2, %3;" : "=l"(d) : "l"(a), "l"(b), "l"(c)); return d;
}
__device__ __forceinline__ ull pack2f(float x, float y) {
    ull d; asm("mov.b64 %0, {%1, %2};" : "=l"(d) : "f"(x), "f"(y)); return d;
}
__device__ __forceinline__ ull packdup(float x) {
    ull d; asm("mov.b64 %0, {%1, %1};" : "=l"(d) : "f"(x)); return d;
}
__device__ __forceinline__ float2 unpack2(ull v) {
    float2 r; asm("mov.b64 {%0, %1}, %2;" : "=f"(r.x), "=f"(r.y) : "l"(v)); return r;
}

// ---------------- kernel 0: AoS -> SoA prep + counter reset ----------------
__global__ void __launch_bounds__(256) k_prep(const float* __restrict__ pts) {
    int i = blockIdx.x * 256 + threadIdx.x;
    if (i == 0) g_ctr = 0;
    if (i < N_PTS) {
        g_xy[i] = make_float2(pts[i * 7], pts[i * 7 + 1]);
        g_z[i] = pts[i * 7 + 2];
    }
}

// ---------------- kernel 0b: all weight packing in ONE launch ----------------
__global__ void __launch_bounds__(128) k_wpack_all(const float* __restrict__ pe_w2,
                                                   const float* __restrict__ q_w,
                                                   const float* __restrict__ o_w1,
                                                   const float* __restrict__ o_w2) {
    int b = blockIdx.x, c2 = threadIdx.x;
    const float* W; int off, j2;
    if (b < 128)      { W = pe_w2; off = PW_PE2; j2 = b; }
    else if (b < 256) { W = q_w;   off = PW_QW;  j2 = b - 128; }
    else if (b < 512) { W = o_w1;  off = PW_OW1; j2 = b - 256; }
    else              { W = o_w2;  off = PW_OW2; j2 = b - 512; }
    const float* r0 = W + (2 * j2) * HID + 2 * c2;
    const float* r1 = W + (2 * j2 + 1) * HID + 2 * c2;
    g_pw[off + j2 * 128 + c2] = make_float4(r0[0], r1[0], r0[1], r1[1]);
}

// ---------------- kernel 1: fm = img^T @ f_w + f_b (persistent, f32x2) ----------------
__global__ void __launch_bounds__(256, 2) k_fm(const float* __restrict__ img,
                                               const float* __restrict__ fw,
                                               const float* __restrict__ fb) {
    extern __shared__ float smf[];
    float* w_s = smf;                 // 96*256, loaded once
    float* a_s = smf + C_IMG * HID;   // 96*FM_PIX, layout [c][pi], reloaded per tile
    int tid = threadIdx.x;
    for (int i = tid; i < C_IMG * HID; i += 256) w_s[i] = fw[i];
    float b = fb[tid];
    ull bb = pack2f(b, b);

    for (int t = blockIdx.x; t < NPIX / FM_PIX; t += FM_GRID) {
        int p0 = t * FM_PIX;
        __syncthreads();   // previous tile's a_s readers done (also covers w_s load on iter 0)
        for (int i = tid; i < C_IMG * FM_PIX; i += 256) {
            int c = i / FM_PIX, pi = i - c * FM_PIX;
            a_s[c * FM_PIX + pi] = img[c * NPIX + p0 + pi];
        }
        __syncthreads();
        ull acc[FM_PIX / 2];   // pixel pairs
#pragma unroll
        for (int i = 0; i < FM_PIX / 2; i++) acc[i] = bb;
#pragma unroll 4
        for (int c = 0; c < C_IMG; c++) {
            ull wd = packdup(w_s[c * HID + tid]);
            const ulonglong2* ap = (const ulonglong2*)&a_s[c * FM_PIX];
#pragma unroll
            for (int q = 0; q < FM_PIX / 4; q++) {
                ulonglong2 av = ap[q];
                acc[2 * q + 0] = ffma2(av.x, wd, acc[2 * q + 0]);
                acc[2 * q + 1] = ffma2(av.y, wd, acc[2 * q + 1]);
            }
        }
#pragma unroll
        for (int i = 0; i < FM_PIX / 2; i++) {
            float2 r = unpack2(acc[i]);
            g_fm[(p0 + 2 * i + 0) * HID + tid] = r.x;
            g_fm[(p0 + 2 * i + 1) * HID + tid] = r.y;
        }
    }
}

// ---------------- kernel 2: per-box selection + knn/density + projection ----------------
__global__ void __launch_bounds__(256) k_sel(const float* __restrict__ pts,
                                             const float* __restrict__ boxes,
                                             const float* __restrict__ proj,
                                             float* __restrict__ out_counts) {
    __shared__ unsigned long long keys[CAND_MAX];
    __shared__ int cnt_s;
    __shared__ int selidx[KMAX];
    __shared__ float nl_s[KMAX * 3];
    __shared__ float dmat[KMAX * KMAX];

    int p = blockIdx.x, tid = threadIdx.x;
    if (tid == 0) cnt_s = 0;
    __syncthreads();

    float cx = boxes[p * 7 + 0], cy = boxes[p * 7 + 1], cz = boxes[p * 7 + 2];
    float dx = boxes[p * 7 + 3], dy = boxes[p * 7 + 4], dz = boxes[p * 7 + 5];
    float yaw = boxes[p * 7 + 6];
    float cth = cosf(yaw), sth = sinf(yaw);
    float hx = dx * 0.5f, hy = dy * 0.5f, hz = dz * 0.5f;
    float ddx = fmaxf(dx, 0.001f), ddy = fmaxf(dy, 0.001f), ddz = fmaxf(dz, 0.001f);

    // scan with hand-batched MLP=4: issue 4 independent xy loads before any branch
#define SEL_PROC(XY, IDX)                                                              \
    {                                                                                  \
        float rx = (XY).x - cx, ry = (XY).y - cy;                                      \
        float lx = __fadd_rn(__fmul_rn(rx, cth), __fmul_rn(ry, sth));                  \
        float ly = __fsub_rn(__fmul_rn(ry, cth), __fmul_rn(rx, sth));                  \
        if (fabsf(lx) <= hx && fabsf(ly) <= hy) {                                      \
            float rz = g_z[IDX] - cz;                                                  \
            if (fabsf(rz) <= hz) {                                                     \
                float nx = lx / ddx, ny = ly / ddy;                                    \
                float planar = sqrtf(nx * nx + ny * ny);                               \
                int pos = atomicAdd(&cnt_s, 1);                                        \
                if (pos < CAND_MAX)                                                    \
                    keys[pos] = ((unsigned long long)__float_as_uint(planar) << 32)    \
                                | (unsigned)(IDX);                                     \
            }                                                                          \
        }                                                                              \
    }
    {
        const int NFULL = (N_PTS / 1024) * 1024;   // 49152
        for (int i0 = 0; i0 < NFULL; i0 += 1024) {
            int i = i0 + tid;
            float2 a0 = g_xy[i];
            float2 a1 = g_xy[i + 256];
            float2 a2 = g_xy[i + 512];
            float2 a3 = g_xy[i + 768];
            SEL_PROC(a0, i)
            SEL_PROC(a1, i + 256)
            SEL_PROC(a2, i + 512)
            SEL_PROC(a3, i + 768)
        }
        for (int i = NFULL + tid; i < N_PTS; i += 256) {
            float2 a = g_xy[i];
            SEL_PROC(a, i)
        }
    }
#undef SEL_PROC
    __syncthreads();
    int cnt = cnt_s;
    int ncand = min(cnt, CAND_MAX);
    int m = min(cnt, KMAX);

    // exact top-64 by (planar, idx) via rank-select (matches lax.top_k tie-break)
    for (int i = tid; i < ncand; i += 256) {
        unsigned long long ki = keys[i];
        int rank = 0;
        for (int j = 0; j < ncand; j++) rank += (keys[j] < ki) ? 1 : 0;
        if (rank < KMAX) selidx[rank] = (int)(ki & 0xffffffffu);
    }
    __syncthreads();

    if (tid < KMAX) {
        int k = tid;
        long base = (long)p * KMAX + k;
        if (k < m) {
            int i = selidx[k];
            float px = pts[i * 7], py = pts[i * 7 + 1], pz = pts[i * 7 + 2];
            float rx = px - cx, ry = py - cy, rz = pz - cz;
            float lx = __fadd_rn(__fmul_rn(rx, cth), __fmul_rn(ry, sth));
            float ly = __fsub_rn(__fmul_rn(ry, cth), __fmul_rn(rx, sth));
            float nx = lx / ddx, ny = ly / ddy, nz = rz / ddz - 0.5f;
            nl_s[k * 3] = nx; nl_s[k * 3 + 1] = ny; nl_s[k * 3 + 2] = nz;
            g_tok[base * 8 + 0] = nx; g_tok[base * 8 + 1] = ny; g_tok[base * 8 + 2] = nz;
            g_tok[base * 8 + 3] = pts[i * 7 + 3];
            g_tok[base * 8 + 4] = pts[i * 7 + 4];
            g_tok[base * 8 + 5] = pts[i * 7 + 5];
            g_tok[base * 8 + 6] = pts[i * 7 + 6];
            // projection
            float h0 = proj[0] * px + proj[1] * py + proj[2] * pz + proj[3];
            float h1 = proj[4] * px + proj[5] * py + proj[6] * pz + proj[7];
            float h2 = proj[8] * px + proj[9] * py + proj[10] * pz + proj[11];
            float depth = h2;
            float safe = (fabsf(depth) > 0.001f) ? depth : 0.001f;
            float rxx = 2.f * (h0 / safe) / 1279.f - 1.f;
            float ryy = 2.f * (h1 / safe) / 383.f - 1.f;
            int v = (depth > 0.1f) && (fabsf(rxx) <= 1.f) && (fabsf(ryy) <= 1.f);
            g_refs[base * 2] = rxx; g_refs[base * 2 + 1] = ryy;
            g_vm[base] = v ? 1.f : 0.f;
        } else {
            nl_s[k * 3] = nl_s[k * 3 + 1] = nl_s[k * 3 + 2] = 0.f;
            for (int j = 0; j < 8; j++) g_tok[base * 8 + j] = 0.f;
            g_refs[base * 2] = 0.f; g_refs[base * 2 + 1] = 0.f;
            g_vm[base] = 0.f;
        }
    }
    __syncthreads();

    const float INF = __int_as_float(0x7f800000);
    for (int e = tid; e < KMAX * KMAX; e += 256) {
        int i = e >> 6, j = e & 63;
        float v = INF;
        if (i < m && j < m) {
            float a = nl_s[i * 3] - nl_s[j * 3];
            float b = nl_s[i * 3 + 1] - nl_s[j * 3 + 1];
            float c = nl_s[i * 3 + 2] - nl_s[j * 3 + 2];
            v = sqrtf(a * a + b * b + c * c + 1e-12f);
        }
        dmat[e] = v;
    }
    __syncthreads();
    if (tid < KMAX && tid < m) {
        int k = tid;
        float b0 = INF, b1 = INF, b2 = INF, b3 = INF;
        for (int j = 0; j < m; j++) {
            float v = dmat[k * KMAX + j];
            if (v < b0)      { b3 = b2; b2 = b1; b1 = b0; b0 = v; }
            else if (v < b1) { b3 = b2; b2 = b1; b1 = v; }
            else if (v < b2) { b3 = b2; b2 = v; }
            else if (v < b3) { b3 = v; }
        }
        int mm = min(m, 4);
        float nb = 0.f;
        if (mm > 1) nb += b1;
        if (mm > 2) nb += b2;
        if (mm > 3) nb += b3;
        float nnb = (float)max(mm - 1, 1);
        g_tok[((long)p * KMAX + k) * 8 + 7] = expf(-nb / nnb);
    }
    if (tid == 0) { g_m[p] = m; out_counts[p] = (float)cnt; }
}

// ---------------- packed slot-GEMM: 2 channels x 8 slots, prepacked weights ----------------
// acc[i]   = (even-j sum, odd-j sum) channel 2c2,   slot s0+i
// acc[8+i] = (even-j sum, odd-j sum) channel 2c2+1, slot s0+i
__device__ __forceinline__ void jacc2_init(ull* acc, const float* __restrict__ B, int ch2) {
    float2 b = *(const float2*)&B[ch2];
    ull b0 = pack2f(b.x, 0.f), b1 = pack2f(b.y, 0.f);
#pragma unroll
    for (int i = 0; i < 8; i++) { acc[i] = b0; acc[8 + i] = b1; }
}

__device__ __forceinline__ void jacc2_gemm(ull* acc, const float* A,
                                           const float4* __restrict__ PW, int s0, int c2) {
#pragma unroll 2
    for (int j4 = 0; j4 < HID / 4; j4++) {
        // rows 4j4,4j4+1 and 4j4+2,4j4+3, both channels, pre-packed
        ulonglong2 w0 = *(const ulonglong2*)&PW[(2 * j4 + 0) * 128 + c2];
        ulonglong2 w1 = *(const ulonglong2*)&PW[(2 * j4 + 1) * 128 + c2];
#pragma unroll
        for (int i = 0; i < 8; i++) {
            ulonglong2 av = *(const ulonglong2*)&A[(s0 + i) * HID + 4 * j4];
            acc[i]     = ffma2(av.x, w0.x, acc[i]);
            acc[i]     = ffma2(av.y, w1.x, acc[i]);
            acc[8 + i] = ffma2(av.x, w0.y, acc[8 + i]);
            acc[8 + i] = ffma2(av.y, w1.y, acc[8 + i]);
        }
    }
}

// MODE: 0 plain, 1 relu, 2 multiply-by-VM, 3 add-into-OUT
template <int MODE>
__device__ __forceinline__ void jacc2_store(float* OUT, const ull* acc, int s0, int ch2,
                                            const float* VMp) {
#pragma unroll
    for (int i = 0; i < 8; i++) {
        float2 p0 = unpack2(acc[i]), p1 = unpack2(acc[8 + i]);
        float v0 = p0.x + p0.y, v1 = p1.x + p1.y;
        if (MODE == 1) { v0 = fmaxf(v0, 0.f); v1 = fmaxf(v1, 0.f); }
        if (MODE == 2) { float vm = VMp[s0 + i]; v0 *= vm; v1 *= vm; }
        if (MODE == 3) {
            float2 e = *(const float2*)&OUT[(s0 + i) * HID + ch2];
            v0 += e.x; v1 += e.y;
        }
        *(float2*)&OUT[(s0 + i) * HID + ch2] = make_float2(v0, v1);
    }
}

// ---------------- kernel 3: persistent per-box MLP chain (512 threads) ----------------
__global__ void __launch_bounds__(512, 1) k_mlp(
    const float* __restrict__ pe_w1, const float* __restrict__ pe_b1,
    const float* __restrict__ pe_b2,
    const float* __restrict__ q_b,
    const float* __restrict__ off_w, const float* __restrict__ off_b,
    const float* __restrict__ wt_w,  const float* __restrict__ wt_b,
    const float* __restrict__ o_b1,
    const float* __restrict__ o_b2,
    const float* __restrict__ score_w, const float* __restrict__ score_b,
    float* __restrict__ out) {
    extern __shared__ float sm[];
    float* H   = sm;                 // 64*256 : h, later fused (in place)
    float* Q   = H  + KMAX * HID;    // 64*256 : h1, later q*vm
    float* CX  = Q  + KMAX * HID;    // 64*256 : context, o1 overlay per tile
    float* TOK = CX + KMAX * HID;    // 64*8
    float* REF = TOK + KMAX * 8;     // 64*2
    float* VMs = REF + KMAX * 2;     // 64
    float* OFS = VMs + KMAX;         // 64*8
    float* WTS = OFS + KMAX * 8;     // 64*4
    float* LG  = WTS + KMAX * 4;     // 64
    float* PW  = LG + KMAX;          // 64
    __shared__ int p_s;

    int tid = threadIdx.x;
    int d = tid & 255;        // output channel (scalar phases)
    int tg = tid >> 8;        // tile group 0/1
    int warp = tid >> 5, lane = tid & 31;
    int half = (tid >> 7) & 1;      // slot-half within group
    int c2 = tid & 127;             // channel-pair index
    int ch2 = c2 * 2;               // channel base

    while (true) {
        if (tid == 0) p_s = atomicAdd(&g_ctr, 1);
        __syncthreads();
        int p = p_s;
        if (p >= P_BOX) break;
        int m = g_m[p];
        if (m > 0) {
            int mt = (m + 15) & ~15;
            long base = (long)p * KMAX;

            for (int i = tid; i < mt * 8; i += 512) TOK[i] = g_tok[base * 8 + i];
            for (int i = tid; i < mt * 2; i += 512) REF[i] = g_refs[base * 2 + i];
            for (int i = tid; i < mt; i += 512) VMs[i] = g_vm[base + i];
            __syncthreads();

            // h1 = relu(tok @ pe_w1 + b1) -> Q   (each group does alternate slots)
            {
                float w[8];
#pragma unroll
                for (int j = 0; j < 8; j++) w[j] = pe_w1[j * HID + d];
                float b = pe_b1[d];
                for (int k = tg; k < mt; k += 2) {
                    float acc = b;
#pragma unroll
                    for (int j = 0; j < 8; j++) acc = fmaf(TOK[k * 8 + j], w[j], acc);
                    Q[k * HID + d] = fmaxf(acc, 0.f);
                }
            }
            __syncthreads();

            // h = h1 @ pe_w2 + b2 -> H
            for (int k0 = tg * 16; k0 < mt; k0 += 32) {
                int s0 = k0 + half * 8;
                ull acc[16];
                jacc2_init(acc, pe_b2, ch2);
                jacc2_gemm(acc, Q, g_pw + PW_PE2, s0, c2);
                jacc2_store<0>(H, acc, s0, ch2, nullptr);
            }
            __syncthreads();

            // heads: offs = tanh(h@off_w+off_b)*0.04 ; wts = softmax(h@wt_w+wt_b)
            for (int k = warp; k < mt; k += 16) {
                float po[12];
#pragma unroll
                for (int i = 0; i < 12; i++) po[i] = 0.f;
                for (int j = lane; j < HID; j += 32) {
                    float hv = H[k * HID + j];
#pragma unroll
                    for (int i = 0; i < 8; i++) po[i] = fmaf(hv, off_w[j * 8 + i], po[i]);
#pragma unroll
                    for (int i = 0; i < 4; i++) po[8 + i] = fmaf(hv, wt_w[j * 4 + i], po[8 + i]);
                }
#pragma unroll
                for (int i = 0; i < 12; i++) {
#pragma unroll
                    for (int o = 16; o > 0; o >>= 1) po[i] += __shfl_xor_sync(0xffffffffu, po[i], o);
                }
                if (lane == 0) {
#pragma unroll
                    for (int i = 0; i < 8; i++) OFS[k * 8 + i] = tanhf(po[i] + off_b[i]) * 0.04f;
                    float l0 = po[8] + wt_b[0], l1 = po[9] + wt_b[1];
                    float l2 = po[10] + wt_b[2], l3 = po[11] + wt_b[3];
                    float mx = fmaxf(fmaxf(l0, l1), fmaxf(l2, l3));
                    float e0 = expf(l0 - mx), e1 = expf(l1 - mx), e2 = expf(l2 - mx), e3 = expf(l3 - mx);
                    float inv = 1.f / (e0 + e1 + e2 + e3);
                    WTS[k * 4 + 0] = e0 * inv; WTS[k * 4 + 1] = e1 * inv;
                    WTS[k * 4 + 2] = e2 * inv; WTS[k * 4 + 3] = e3 * inv;
                }
            }
            __syncthreads();

            // q*vm -> Q (h1 dead)
            for (int k0 = tg * 16; k0 < mt; k0 += 32) {
                int s0 = k0 + half * 8;
                ull acc[16];
                jacc2_init(acc, q_b, ch2);
                jacc2_gemm(acc, H, g_pw + PW_QW, s0, c2);
                jacc2_store<2>(Q, acc, s0, ch2, VMs);
            }

            // sampling -> CX: thread covers 4 channels, 8 slots per pass
            {
                int kq = tid >> 6;          // 0..7 slot offset
                int cq = (tid & 63) << 2;   // channel base (float4)
                for (int k0 = 0; k0 < mt; k0 += 8) {
                    int k = k0 + kq;
                    float4 ctx = make_float4(0.f, 0.f, 0.f, 0.f);
                    if (VMs[k] != 0.f) {
                        float rx = REF[k * 2], ry = REF[k * 2 + 1];
#pragma unroll
                        for (int s2 = 0; s2 < 4; s2++) {
                            float gx = fminf(fmaxf(rx + OFS[k * 8 + s2 * 2 + 0], -1.2f), 1.2f);
                            float gy = fminf(fmaxf(ry + OFS[k * 8 + s2 * 2 + 1], -1.2f), 1.2f);
                            float px = (gx + 1.f) * 0.5f * (float)(WF - 1);
                            float py = (gy + 1.f) * 0.5f * (float)(HF - 1);
                            float x0f = floorf(px), y0f = floorf(py);
                            int x0 = (int)x0f, y0 = (int)y0f;
                            float wx = px - x0f, wy = py - y0f;
                            bool xin0 = (x0 >= 0) && (x0 < WF), xin1 = (x0 + 1 >= 0) && (x0 + 1 < WF);
                            bool yin0 = (y0 >= 0) && (y0 < HF), yin1 = (y0 + 1 >= 0) && (y0 + 1 < HF);
                            float4 s00 = make_float4(0.f, 0.f, 0.f, 0.f), s10 = s00, s01 = s00, s11 = s00;
                            if (xin0 && yin0) s00 = *(const float4*)&g_fm[(y0 * WF + x0) * HID + cq];
                            if (xin1 && yin0) s10 = *(const float4*)&g_fm[(y0 * WF + x0 + 1) * HID + cq];
                            if (xin0 && yin1) s01 = *(const float4*)&g_fm[((y0 + 1) * WF + x0) * HID + cq];
                            if (xin1 && yin1) s11 = *(const float4*)&g_fm[((y0 + 1) * WF + x0 + 1) * HID + cq];
                            float w00 = (1.f - wx) * (1.f - wy), w10 = wx * (1.f - wy);
                            float w01 = (1.f - wx) * wy,         w11 = wx * wy;
                            float ws = WTS[k * 4 + s2];
                            ctx.x += (s00.x * w00 + s10.x * w10 + s01.x * w01 + s11.x * w11) * ws;
                            ctx.y += (s00.y * w00 + s10.y * w10 + s01.y * w01 + s11.y * w11) * ws;
                            ctx.z += (s00.z * w00 + s10.z * w10 + s01.z * w01 + s11.z * w11) * ws;
                            ctx.w += (s00.w * w00 + s10.w * w10 + s01.w * w01 + s11.w * w11) * ws;
                        }
                    }
                    *(float4*)&CX[k * HID + cq] = ctx;
                }
            }
            __syncthreads();

            // o-MLP per 16-slot tile (group-local, named barriers):
            // o1 = relu([q*vm, ctx] @ o_w1 + b1)  stored over the dead CX tile
            // img_tok = o1 @ o_w2 + b2 ; fused = h + img_tok (in place on H)
            for (int k0 = tg * 16; k0 < mt; k0 += 32) {
                int s0 = k0 + half * 8;
                ull acc[16];
                jacc2_init(acc, o_b1, ch2);
                jacc2_gemm(acc, Q, g_pw + PW_OW1, s0, c2);
                jacc2_gemm(acc, CX, g_pw + PW_OW1 + 16384, s0, c2);
                BARG(tg);   // group's CX-tile reads done
                jacc2_store<1>(CX, acc, s0, ch2, nullptr);
                BARG(tg);   // o1 visible to group
                ull acc2[16];
                jacc2_init(acc2, o_b2, ch2);
                jacc2_gemm(acc2, CX, g_pw + PW_OW2, s0, c2);
                jacc2_store<3>(H, acc2, s0, ch2, nullptr);
            }
            __syncthreads();

            // logits (only valid slots)
            for (int k = warp; k < m; k += 16) {
                float pl = 0.f;
                for (int j = lane; j < HID; j += 32) pl = fmaf(H[k * HID + j], score_w[j], pl);
#pragma unroll
                for (int o = 16; o > 0; o >>= 1) pl += __shfl_xor_sync(0xffffffffu, pl, o);
                if (lane == 0) LG[k] = pl + score_b[0];
            }
            __syncthreads();

            // softmax over k<m (warp 0)
            if (tid < 32) {
                float mx = -3.4e38f;
                for (int k = tid; k < m; k += 32) mx = fmaxf(mx, LG[k]);
#pragma unroll
                for (int o = 16; o > 0; o >>= 1) mx = fmaxf(mx, __shfl_xor_sync(0xffffffffu, mx, o));
                float ssum = 0.f;
                for (int k = tid; k < m; k += 32) { float e = expf(LG[k] - mx); PW[k] = e; ssum += e; }
#pragma unroll
                for (int o = 16; o > 0; o >>= 1) ssum += __shfl_xor_sync(0xffffffffu, ssum, o);
                float inv = 1.f / ssum;
                for (int k = tid; k < m; k += 32) PW[k] *= inv;
            }
            __syncthreads();

            if (tid < 256) {
                float pooled = 0.f;
                for (int k = 0; k < m; k++) pooled = fmaf(PW[k], H[k * HID + tid], pooled);
                out[p * HID + tid] = pooled;
            }
        } else {
            if (tid < 256) out[p * HID + tid] = 0.f;
        }
        __syncthreads();  // protect smem reuse + p_s for next iteration
    }
}

// ---------------- launcher ----------------
extern "C" void kernel_launch(void* const* d_in, const int* in_sizes, int n_in,
                              void* d_out, int out_size) {
    const float* points  = (const float*)d_in[0];
    const float* boxes   = (const float*)d_in[1];
    const float* img     = (const float*)d_in[2];
    const float* proj    = (const float*)d_in[3];
    const float* pe_w1   = (const float*)d_in[4];
    const float* pe_b1   = (const float*)d_in[5];
    const float* pe_w2   = (const float*)d_in[6];
    const float* pe_b2   = (const float*)d_in[7];
    const float* q_w     = (const float*)d_in[8];
    const float* q_b     = (const float*)d_in[9];
    const float* f_w     = (const float*)d_in[10];
    const float* f_b     = (const float*)d_in[11];
    const float* off_w   = (const float*)d_in[12];
    const float* off_b   = (const float*)d_in[13];
    const float* wt_w    = (const float*)d_in[14];
    const float* wt_b    = (const float*)d_in[15];
    const float* o_w1    = (const float*)d_in[16];
    const float* o_b1    = (const float*)d_in[17];
    const float* o_w2    = (const float*)d_in[18];
    const float* o_b2    = (const float*)d_in[19];
    const float* score_w = (const float*)d_in[20];
    const float* score_b = (const float*)d_in[21];
    float* out = (float*)d_out;

    static cudaStream_t s2 = nullptr;
    static cudaEvent_t ev_fork = nullptr, ev_join = nullptr;
    if (s2 == nullptr) {
        cudaStreamCreateWithFlags(&s2, cudaStreamNonBlocking);
        cudaEventCreateWithFlags(&ev_fork, cudaEventDisableTiming);
        cudaEventCreateWithFlags(&ev_join, cudaEventDisableTiming);
    }

    const int smem_fm  = (C_IMG * HID + C_IMG * FM_PIX) * 4;                 // 110592
    const int smem_mlp = (3 * KMAX * HID + KMAX * 8 + KMAX * 2 +
                          KMAX + KMAX * 8 + KMAX * 4 + KMAX + KMAX) * 4;    // 203008

    cudaFuncSetAttribute(k_fm,  cudaFuncAttributeMaxDynamicSharedMemorySize, smem_fm);
    cudaFuncSetAttribute(k_mlp, cudaFuncAttributeMaxDynamicSharedMemorySize, smem_mlp);

    // fork: wpack + k_fm (persistent) on s2, prep+sel on default stream, join before k_mlp
    cudaEventRecord(ev_fork, 0);
    cudaStreamWaitEvent(s2, ev_fork, 0);
    k_wpack_all<<<640, 128, 0, s2>>>(pe_w2, q_w, o_w1, o_w2);
    k_fm<<<FM_GRID, 256, smem_fm, s2>>>(img, f_w, f_b);
    cudaEventRecord(ev_join, s2);

    k_prep<<<(N_PTS + 255) / 256, 256>>>(points);
    k_sel<<<P_BOX, 256>>>(points, boxes, proj, out + P_BOX * HID);

    cudaStreamWaitEvent(0, ev_join, 0);
    k_mlp<<<152, 512, smem_mlp>>>(pe_w1, pe_b1, pe_b2, q_b,
                                  off_w, off_b, wt_w, wt_b, o_b1,
                                  o_b2, score_w, score_b, out);
}